// round 1
// baseline (speedup 1.0000x reference)
#include <cuda_runtime.h>

// Derived constants computed on-device (graph-capturable, no host sync):
// g_c[0].xyz = weights[0][i] * 0.5          (folded into sincos argument)
// g_c[1].xyz = cos(weights[1][i] * 0.5)
// g_c[2].xyz = sin(weights[1][i] * 0.5)
__device__ float4 g_c[3];

__global__ void qfl_precompute(const float* __restrict__ w) {
    if (threadIdx.x == 0) {
        float4 h0, cv, sv;
        h0.x = w[0] * 0.5f; h0.y = w[1] * 0.5f; h0.z = w[2] * 0.5f; h0.w = 0.f;
        float s, c;
        sincosf(w[3] * 0.5f, &s, &c); cv.x = c; sv.x = s;
        sincosf(w[4] * 0.5f, &s, &c); cv.y = c; sv.y = s;
        sincosf(w[5] * 0.5f, &s, &c); cv.z = c; sv.z = s;
        cv.w = 0.f; sv.w = 0.f;
        g_c[0] = h0; g_c[1] = cv; g_c[2] = sv;
    }
}

__global__ void __launch_bounds__(256)
qfl_kernel(const float4* __restrict__ x, float* __restrict__ out, int B) {
    int i = blockIdx.x * 256 + threadIdx.x;
    if (i >= B) return;

    // Uniform loads: L1-hit broadcast LDG.128 x3
    const float4 h0 = g_c[0];
    const float4 C  = g_c[1];
    const float4 S  = g_c[2];

    const float4 xv = x[i];

    // Reference uses the literal 3.14159 (not full-precision pi) — match it.
    const float HPI = 3.14159f * 0.5f;

    // Encoding RY + layer-0 RY compose: half-angle = x_i*(pi/2) + w0_i/2
    float s0, c0, s1, c1, s2, c2;
    __sincosf(fmaf(xv.x, HPI, h0.x), &s0, &c0);
    __sincosf(fmaf(xv.y, HPI, h0.y), &s1, &c1);
    __sincosf(fmaf(xv.z, HPI, h0.z), &s2, &c2);

    // Product state amplitudes a[b0][b1][b2] = u0[b0]*u1[b1]*u2[b2]
    float w00 = c0 * c1, w01 = c0 * s1, w10 = s0 * c1, w11 = s0 * s1;
    float a000 = w00 * c2, a001 = w00 * s2, a010 = w01 * c2, a011 = w01 * s2;
    float a100 = w10 * c2, a101 = w10 * s2, a110 = w11 * c2, a111 = w11 * s2;

    // CNOT(0,1) then CNOT(1,2): d[b0][b1][b2] = a[b0][b1^b0][b2^b1]  (free renames)
    float d000 = a000, d001 = a001, d010 = a011, d011 = a010;
    float d100 = a110, d101 = a111, d110 = a101, d111 = a100;

    // Layer-1 RY on wire 0 (C.x, S.x): rotate pairs (d0yz, d1yz)
    float e000 = fmaf(C.x, d000, -S.x * d100);
    float e100 = fmaf(S.x, d000,  C.x * d100);
    float e001 = fmaf(C.x, d001, -S.x * d101);
    float e101 = fmaf(S.x, d001,  C.x * d101);
    float e010 = fmaf(C.x, d010, -S.x * d110);
    float e110 = fmaf(S.x, d010,  C.x * d110);
    float e011 = fmaf(C.x, d011, -S.x * d111);
    float e111 = fmaf(S.x, d011,  C.x * d111);

    // RY on wire 1 (C.y, S.y): rotate pairs (ex0z, ex1z)
    float f000 = fmaf(C.y, e000, -S.y * e010);
    float f010 = fmaf(S.y, e000,  C.y * e010);
    float f001 = fmaf(C.y, e001, -S.y * e011);
    float f011 = fmaf(S.y, e001,  C.y * e011);
    float f100 = fmaf(C.y, e100, -S.y * e110);
    float f110 = fmaf(S.y, e100,  C.y * e110);
    float f101 = fmaf(C.y, e101, -S.y * e111);
    float f111 = fmaf(S.y, e101,  C.y * e111);

    // RY on wire 2 (C.z, S.z): rotate pairs (fxy0, fxy1)
    float g000 = fmaf(C.z, f000, -S.z * f001);
    float g001 = fmaf(S.z, f000,  C.z * f001);
    float g010 = fmaf(C.z, f010, -S.z * f011);
    float g011 = fmaf(S.z, f010,  C.z * f011);
    float g100 = fmaf(C.z, f100, -S.z * f101);
    float g101 = fmaf(S.z, f100,  C.z * f101);
    float g110 = fmaf(C.z, f110, -S.z * f111);
    float g111 = fmaf(S.z, f110,  C.z * f111);

    // Final CNOT(0,1), CNOT(1,2) are again index permutations; fold them into
    // the sign pattern of the Z expectations. With p_xyz = g_xyz^2 (pre-CNOT
    // labels), the measured-basis sums reduce to:
    //   Z0 = (p000+p001+p010+p011) - (p100+p101+p110+p111)
    //   Z1 = (p000+p001+p110+p111) - (p010+p011+p100+p101)
    //   Z2 = (p000+p011+p101+p110) - (p001+p010+p100+p111)
    float p000 = g000 * g000, p001 = g001 * g001;
    float p010 = g010 * g010, p011 = g011 * g011;
    float p100 = g100 * g100, p101 = g101 * g101;
    float p110 = g110 * g110, p111 = g111 * g111;

    float A = p000 + p001, Bp = p010 + p011, Cp = p100 + p101, D = p110 + p111;
    float z0 = (A + Bp) - (Cp + D);
    float z1 = (A + D) - (Bp + Cp);

    float u = p000 - p001, v = p010 - p011, w = p100 - p101, t = p110 - p111;
    float z2 = (u - v) + (t - w);

    float* o = out + 3 * i;
    o[0] = z0;
    o[1] = z1;
    o[2] = z2;
}

extern "C" void kernel_launch(void* const* d_in, const int* in_sizes, int n_in,
                              void* d_out, int out_size) {
    const float* x = (const float*)d_in[0];        // (B, 4) float32
    const float* w = (const float*)d_in[1];        // (2, 3) float32
    float* out = (float*)d_out;                    // (B, 3) float32
    int B = in_sizes[0] / 4;

    qfl_precompute<<<1, 32>>>(w);
    qfl_kernel<<<(B + 255) / 256, 256>>>((const float4*)x, out, B);
}

// round 2
// speedup vs baseline: 1.0443x; 1.0443x over previous
#include <cuda_runtime.h>

// Single-kernel version: weight-derived constants computed per-block into smem
// (thread 0 only), batch processed with 2 elements per thread for ILP/MLP=2.
//
// Reference math (3-qubit, 2-layer RY+CNOT circuit) reduced to closed form:
//   - encoding RY(x_i*pi) and layer-0 RY(w0_i) compose into one angle
//   - CNOTs are index permutations (free register renames)
//   - final CNOT pair folded into the sign pattern of the <Z_i> sums

__device__ __forceinline__ void qfl_compute(
    const float4 xv,
    const float h00, const float h01, const float h02,
    const float Cx, const float Cy, const float Cz,
    const float Sx, const float Sy, const float Sz,
    float& z0, float& z1, float& z2)
{
    // Reference uses the literal 3.14159 (not full-precision pi) — match it.
    const float HPI = 3.14159f * 0.5f;

    float s0, c0, s1, c1, s2, c2;
    __sincosf(fmaf(xv.x, HPI, h00), &s0, &c0);
    __sincosf(fmaf(xv.y, HPI, h01), &s1, &c1);
    __sincosf(fmaf(xv.z, HPI, h02), &s2, &c2);

    // Product state amplitudes
    float w00 = c0 * c1, w01 = c0 * s1, w10 = s0 * c1, w11 = s0 * s1;
    float a000 = w00 * c2, a001 = w00 * s2, a010 = w01 * c2, a011 = w01 * s2;
    float a100 = w10 * c2, a101 = w10 * s2, a110 = w11 * c2, a111 = w11 * s2;

    // CNOT(0,1), CNOT(1,2): d[b0][b1][b2] = a[b0][b1^b0][b2^b1]
    float d000 = a000, d001 = a001, d010 = a011, d011 = a010;
    float d100 = a110, d101 = a111, d110 = a101, d111 = a100;

    // Layer-1 RY wire 0
    float e000 = fmaf(Cx, d000, -Sx * d100);
    float e100 = fmaf(Sx, d000,  Cx * d100);
    float e001 = fmaf(Cx, d001, -Sx * d101);
    float e101 = fmaf(Sx, d001,  Cx * d101);
    float e010 = fmaf(Cx, d010, -Sx * d110);
    float e110 = fmaf(Sx, d010,  Cx * d110);
    float e011 = fmaf(Cx, d011, -Sx * d111);
    float e111 = fmaf(Sx, d011,  Cx * d111);

    // wire 1
    float f000 = fmaf(Cy, e000, -Sy * e010);
    float f010 = fmaf(Sy, e000,  Cy * e010);
    float f001 = fmaf(Cy, e001, -Sy * e011);
    float f011 = fmaf(Sy, e001,  Cy * e011);
    float f100 = fmaf(Cy, e100, -Sy * e110);
    float f110 = fmaf(Sy, e100,  Cy * e110);
    float f101 = fmaf(Cy, e101, -Sy * e111);
    float f111 = fmaf(Sy, e101,  Cy * e111);

    // wire 2
    float g000 = fmaf(Cz, f000, -Sz * f001);
    float g001 = fmaf(Sz, f000,  Cz * f001);
    float g010 = fmaf(Cz, f010, -Sz * f011);
    float g011 = fmaf(Sz, f010,  Cz * f011);
    float g100 = fmaf(Cz, f100, -Sz * f101);
    float g101 = fmaf(Sz, f100,  Cz * f101);
    float g110 = fmaf(Cz, f110, -Sz * f111);
    float g111 = fmaf(Sz, f110,  Cz * f111);

    // Probabilities; final CNOTs folded into sign patterns.
    float p000 = g000 * g000, p001 = g001 * g001;
    float p010 = g010 * g010, p011 = g011 * g011;
    float p100 = g100 * g100, p101 = g101 * g101;
    float p110 = g110 * g110, p111 = g111 * g111;

    float A = p000 + p001, Bp = p010 + p011, Cp = p100 + p101, D = p110 + p111;
    z0 = (A + Bp) - (Cp + D);
    z1 = (A + D) - (Bp + Cp);

    float u = p000 - p001, v = p010 - p011, w = p100 - p101, t = p110 - p111;
    z2 = (u - v) + (t - w);
}

__global__ void __launch_bounds__(128)
qfl_kernel(const float4* __restrict__ x, float* __restrict__ out,
           const float* __restrict__ w, int T /* = B/2 */) {
    __shared__ float sh[9];  // [0..2]=w0*0.5, [3..5]=cos(w1*0.5), [6..8]=sin(w1*0.5)
    if (threadIdx.x == 0) {
        float w0 = w[0], w1 = w[1], w2 = w[2];
        float w3 = w[3], w4 = w[4], w5 = w[5];
        sh[0] = w0 * 0.5f; sh[1] = w1 * 0.5f; sh[2] = w2 * 0.5f;
        float s, c;
        __sincosf(w3 * 0.5f, &s, &c); sh[3] = c; sh[6] = s;
        __sincosf(w4 * 0.5f, &s, &c); sh[4] = c; sh[7] = s;
        __sincosf(w5 * 0.5f, &s, &c); sh[5] = c; sh[8] = s;
    }
    __syncthreads();

    const float h00 = sh[0], h01 = sh[1], h02 = sh[2];
    const float Cx = sh[3], Cy = sh[4], Cz = sh[5];
    const float Sx = sh[6], Sy = sh[7], Sz = sh[8];

    int i = blockIdx.x * 128 + threadIdx.x;
    if (i >= T) return;
    int j = i + T;

    // Front-batched independent loads (MLP=2), both perfectly coalesced.
    const float4 xa = x[i];
    const float4 xb = x[j];

    float az0, az1, az2, bz0, bz1, bz2;
    qfl_compute(xa, h00, h01, h02, Cx, Cy, Cz, Sx, Sy, Sz, az0, az1, az2);
    qfl_compute(xb, h00, h01, h02, Cx, Cy, Cz, Sx, Sy, Sz, bz0, bz1, bz2);

    float* oa = out + 3 * i;
    oa[0] = az0; oa[1] = az1; oa[2] = az2;
    float* ob = out + 3 * j;
    ob[0] = bz0; ob[1] = bz1; ob[2] = bz2;
}

extern "C" void kernel_launch(void* const* d_in, const int* in_sizes, int n_in,
                              void* d_out, int out_size) {
    const float* x = (const float*)d_in[0];   // (B, 4) float32
    const float* w = (const float*)d_in[1];   // (2, 3) float32
    float* out = (float*)d_out;               // (B, 3) float32
    int B = in_sizes[0] / 4;
    int T = B / 2;                            // 2 elements per thread

    qfl_kernel<<<(T + 127) / 128, 128>>>((const float4*)x, out, w, T);
}

// round 3
// speedup vs baseline: 1.1322x; 1.0841x over previous
#include <cuda_runtime.h>

// f32x2 packed-math version: 4 elements/thread as two independent f32x2 SIMD
// chains. Rotation/probability math runs on FFMA2/FMUL2/FADD2 (2 elements per
// instruction), halving issued instruction count — the round-2 limiter.

using u64 = unsigned long long;

__device__ __forceinline__ u64 pack2(float lo, float hi) {
    u64 r; asm("mov.b64 %0, {%1, %2};" : "=l"(r) : "f"(lo), "f"(hi)); return r;
}
__device__ __forceinline__ void unpack2(u64 v, float& lo, float& hi) {
    asm("mov.b64 {%0, %1}, %2;" : "=f"(lo), "=f"(hi) : "l"(v));
}
__device__ __forceinline__ u64 fma2(u64 a, u64 b, u64 c) {
    u64 d; asm("fma.rn.f32x2 %0, %1, %2, %3;" : "=l"(d) : "l"(a), "l"(b), "l"(c)); return d;
}
__device__ __forceinline__ u64 mul2(u64 a, u64 b) {
    u64 d; asm("mul.rn.f32x2 %0, %1, %2;" : "=l"(d) : "l"(a), "l"(b)); return d;
}
__device__ __forceinline__ u64 add2(u64 a, u64 b) {
    u64 d; asm("add.rn.f32x2 %0, %1, %2;" : "=l"(d) : "l"(a), "l"(b)); return d;
}

struct QConsts {
    u64 Cx, Cy, Cz, Sx, Sy, Sz, NSx, NSy, NSz, neg1;
};

// One packed chain: computes z0/z1/z2 (each holding results for 2 elements)
// from packed half-angle sin/cos values.
__device__ __forceinline__ void qfl_chain(
    u64 s0, u64 c0, u64 s1, u64 c1, u64 s2, u64 c2,
    const QConsts& q, u64& z0, u64& z1, u64& z2)
{
    // Product state amplitudes
    u64 w00 = mul2(c0, c1), w01 = mul2(c0, s1), w10 = mul2(s0, c1), w11 = mul2(s0, s1);
    u64 a000 = mul2(w00, c2), a001 = mul2(w00, s2), a010 = mul2(w01, c2), a011 = mul2(w01, s2);
    u64 a100 = mul2(w10, c2), a101 = mul2(w10, s2), a110 = mul2(w11, c2), a111 = mul2(w11, s2);

    // CNOT(0,1), CNOT(1,2): index permutation (free renames)
    u64 d000 = a000, d001 = a001, d010 = a011, d011 = a010;
    u64 d100 = a110, d101 = a111, d110 = a101, d111 = a100;

    // Layer-1 RY wire 0
    u64 e000 = fma2(q.Cx, d000, mul2(q.NSx, d100));
    u64 e100 = fma2(q.Sx, d000, mul2(q.Cx,  d100));
    u64 e001 = fma2(q.Cx, d001, mul2(q.NSx, d101));
    u64 e101 = fma2(q.Sx, d001, mul2(q.Cx,  d101));
    u64 e010 = fma2(q.Cx, d010, mul2(q.NSx, d110));
    u64 e110 = fma2(q.Sx, d010, mul2(q.Cx,  d110));
    u64 e011 = fma2(q.Cx, d011, mul2(q.NSx, d111));
    u64 e111 = fma2(q.Sx, d011, mul2(q.Cx,  d111));

    // wire 1
    u64 f000 = fma2(q.Cy, e000, mul2(q.NSy, e010));
    u64 f010 = fma2(q.Sy, e000, mul2(q.Cy,  e010));
    u64 f001 = fma2(q.Cy, e001, mul2(q.NSy, e011));
    u64 f011 = fma2(q.Sy, e001, mul2(q.Cy,  e011));
    u64 f100 = fma2(q.Cy, e100, mul2(q.NSy, e110));
    u64 f110 = fma2(q.Sy, e100, mul2(q.Cy,  e110));
    u64 f101 = fma2(q.Cy, e101, mul2(q.NSy, e111));
    u64 f111 = fma2(q.Sy, e101, mul2(q.Cy,  e111));

    // wire 2
    u64 g000 = fma2(q.Cz, f000, mul2(q.NSz, f001));
    u64 g001 = fma2(q.Sz, f000, mul2(q.Cz,  f001));
    u64 g010 = fma2(q.Cz, f010, mul2(q.NSz, f011));
    u64 g011 = fma2(q.Sz, f010, mul2(q.Cz,  f011));
    u64 g100 = fma2(q.Cz, f100, mul2(q.NSz, f101));
    u64 g101 = fma2(q.Sz, f100, mul2(q.Cz,  f101));
    u64 g110 = fma2(q.Cz, f110, mul2(q.NSz, f111));
    u64 g111 = fma2(q.Sz, f110, mul2(q.Cz,  f111));

    // Probabilities; final CNOT pair folded into sign patterns.
    u64 p000 = mul2(g000, g000), p001 = mul2(g001, g001);
    u64 p010 = mul2(g010, g010), p011 = mul2(g011, g011);
    u64 p100 = mul2(g100, g100), p101 = mul2(g101, g101);
    u64 p110 = mul2(g110, g110), p111 = mul2(g111, g111);

    u64 A = add2(p000, p001), Bp = add2(p010, p011);
    u64 Cp = add2(p100, p101), D = add2(p110, p111);
    // z0 = (A+Bp) - (Cp+D);  z1 = (A+D) - (Bp+Cp)
    z0 = fma2(q.neg1, add2(Cp, D), add2(A, Bp));
    z1 = fma2(q.neg1, add2(Bp, Cp), add2(A, D));
    // z2 = (p000-p001) - (p010-p011) + (p110-p111) - (p100-p101)
    u64 u = fma2(q.neg1, p001, p000);
    u64 v = fma2(q.neg1, p011, p010);
    u64 w = fma2(q.neg1, p101, p100);
    u64 t = fma2(q.neg1, p111, p110);
    z2 = add2(fma2(q.neg1, v, u), fma2(q.neg1, w, t));
}

__global__ void __launch_bounds__(128)
qfl_kernel(const float4* __restrict__ x, float4* __restrict__ out,
           const float* __restrict__ w, int T /* = B/4 */) {
    __shared__ float sh[9];
    if (threadIdx.x == 0) {
        sh[0] = w[0] * 0.5f; sh[1] = w[1] * 0.5f; sh[2] = w[2] * 0.5f;
        float s, c;
        __sincosf(w[3] * 0.5f, &s, &c); sh[3] = c; sh[6] = s;
        __sincosf(w[4] * 0.5f, &s, &c); sh[4] = c; sh[7] = s;
        __sincosf(w[5] * 0.5f, &s, &c); sh[5] = c; sh[8] = s;
    }
    __syncthreads();

    const float h00 = sh[0], h01 = sh[1], h02 = sh[2];
    QConsts q;
    q.Cx = pack2(sh[3], sh[3]); q.Cy = pack2(sh[4], sh[4]); q.Cz = pack2(sh[5], sh[5]);
    q.Sx = pack2(sh[6], sh[6]); q.Sy = pack2(sh[7], sh[7]); q.Sz = pack2(sh[8], sh[8]);
    q.NSx = pack2(-sh[6], -sh[6]); q.NSy = pack2(-sh[7], -sh[7]); q.NSz = pack2(-sh[8], -sh[8]);
    q.neg1 = pack2(-1.0f, -1.0f);

    int i = blockIdx.x * 128 + threadIdx.x;
    if (i >= T) return;

    // 4 consecutive elements: 64B contiguous read per thread, front-batched.
    const float4 xa = x[4 * i + 0];
    const float4 xb = x[4 * i + 1];
    const float4 xc = x[4 * i + 2];
    const float4 xd = x[4 * i + 3];

    // Reference uses the literal 3.14159 — match it.
    const float HPI = 3.14159f * 0.5f;

    float sa0, ca0, sa1, ca1, sa2, ca2;
    float sb0, cb0, sb1, cb1, sb2, cb2;
    float sc0, cc0, sc1, cc1, sc2, cc2;
    float sd0, cd0, sd1, cd1, sd2, cd2;
    __sincosf(fmaf(xa.x, HPI, h00), &sa0, &ca0);
    __sincosf(fmaf(xa.y, HPI, h01), &sa1, &ca1);
    __sincosf(fmaf(xa.z, HPI, h02), &sa2, &ca2);
    __sincosf(fmaf(xb.x, HPI, h00), &sb0, &cb0);
    __sincosf(fmaf(xb.y, HPI, h01), &sb1, &cb1);
    __sincosf(fmaf(xb.z, HPI, h02), &sb2, &cb2);
    __sincosf(fmaf(xc.x, HPI, h00), &sc0, &cc0);
    __sincosf(fmaf(xc.y, HPI, h01), &sc1, &cc1);
    __sincosf(fmaf(xc.z, HPI, h02), &sc2, &cc2);
    __sincosf(fmaf(xd.x, HPI, h00), &sd0, &cd0);
    __sincosf(fmaf(xd.y, HPI, h01), &sd1, &cd1);
    __sincosf(fmaf(xd.z, HPI, h02), &sd2, &cd2);

    // Chain A = elements (a, b); Chain B = elements (c, d)
    u64 Az0, Az1, Az2, Bz0, Bz1, Bz2;
    qfl_chain(pack2(sa0, sb0), pack2(ca0, cb0),
              pack2(sa1, sb1), pack2(ca1, cb1),
              pack2(sa2, sb2), pack2(ca2, cb2), q, Az0, Az1, Az2);
    qfl_chain(pack2(sc0, sd0), pack2(cc0, cd0),
              pack2(sc1, sd1), pack2(cc1, cd1),
              pack2(sc2, sd2), pack2(cc2, cd2), q, Bz0, Bz1, Bz2);

    float az0, bz0, az1, bz1, az2, bz2;
    float cz0, dz0, cz1, dz1, cz2, dz2;
    unpack2(Az0, az0, bz0); unpack2(Az1, az1, bz1); unpack2(Az2, az2, bz2);
    unpack2(Bz0, cz0, dz0); unpack2(Bz1, cz1, dz1); unpack2(Bz2, cz2, dz2);

    // 12 contiguous floats -> 3x STG.128 (out + 12*i is 16B-aligned)
    float4* o = out + 3 * i;
    o[0] = make_float4(az0, az1, az2, bz0);
    o[1] = make_float4(bz1, bz2, cz0, cz1);
    o[2] = make_float4(cz2, dz0, dz1, dz2);
}

extern "C" void kernel_launch(void* const* d_in, const int* in_sizes, int n_in,
                              void* d_out, int out_size) {
    const float* x = (const float*)d_in[0];   // (B, 4) float32
    const float* w = (const float*)d_in[1];   // (2, 3) float32
    float4* out = (float4*)d_out;             // (B, 3) float32
    int B = in_sizes[0] / 4;
    int T = B / 4;                            // 4 elements per thread

    qfl_kernel<<<(T + 127) / 128, 128>>>((const float4*)x, out, w, T);
}

// round 4
// speedup vs baseline: 1.1572x; 1.0221x over previous
#include <cuda_runtime.h>

// Packed f32x2 math, 2 elements per thread (one packed chain). Rationale:
// round-3 showed ILP=4 starves occupancy (1.73 waves); ILP=2 keeps the packed
// instruction savings while doubling resident warps for latency hiding.

using u64 = unsigned long long;

__device__ __forceinline__ u64 pack2(float lo, float hi) {
    u64 r; asm("mov.b64 %0, {%1, %2};" : "=l"(r) : "f"(lo), "f"(hi)); return r;
}
__device__ __forceinline__ void unpack2(u64 v, float& lo, float& hi) {
    asm("mov.b64 {%0, %1}, %2;" : "=f"(lo), "=f"(hi) : "l"(v));
}
__device__ __forceinline__ u64 fma2(u64 a, u64 b, u64 c) {
    u64 d; asm("fma.rn.f32x2 %0, %1, %2, %3;" : "=l"(d) : "l"(a), "l"(b), "l"(c)); return d;
}
__device__ __forceinline__ u64 mul2(u64 a, u64 b) {
    u64 d; asm("mul.rn.f32x2 %0, %1, %2;" : "=l"(d) : "l"(a), "l"(b)); return d;
}
__device__ __forceinline__ u64 add2(u64 a, u64 b) {
    u64 d; asm("add.rn.f32x2 %0, %1, %2;" : "=l"(d) : "l"(a), "l"(b)); return d;
}

__global__ void __launch_bounds__(256)
qfl_kernel(const float4* __restrict__ x, float2* __restrict__ out,
           const float* __restrict__ w, int T /* = B/2 */) {
    __shared__ float sh[9];
    if (threadIdx.x == 0) {
        sh[0] = w[0] * 0.5f; sh[1] = w[1] * 0.5f; sh[2] = w[2] * 0.5f;
        float s, c;
        __sincosf(w[3] * 0.5f, &s, &c); sh[3] = c; sh[6] = s;
        __sincosf(w[4] * 0.5f, &s, &c); sh[4] = c; sh[7] = s;
        __sincosf(w[5] * 0.5f, &s, &c); sh[5] = c; sh[8] = s;
    }
    __syncthreads();

    const float h00 = sh[0], h01 = sh[1], h02 = sh[2];
    const u64 Cx = pack2(sh[3], sh[3]), Cy = pack2(sh[4], sh[4]), Cz = pack2(sh[5], sh[5]);
    const u64 Sx = pack2(sh[6], sh[6]), Sy = pack2(sh[7], sh[7]), Sz = pack2(sh[8], sh[8]);
    const u64 NSx = pack2(-sh[6], -sh[6]), NSy = pack2(-sh[7], -sh[7]), NSz = pack2(-sh[8], -sh[8]);
    const u64 neg1 = pack2(-1.0f, -1.0f);

    int i = blockIdx.x * 256 + threadIdx.x;
    if (i >= T) return;

    // 2 consecutive elements: 32B contiguous, front-batched MLP=2.
    const float4 xa = x[2 * i + 0];
    const float4 xb = x[2 * i + 1];

    // Reference uses the literal 3.14159 — match it.
    const float HPI = 3.14159f * 0.5f;

    float sa0, ca0, sa1, ca1, sa2, ca2;
    float sb0, cb0, sb1, cb1, sb2, cb2;
    __sincosf(fmaf(xa.x, HPI, h00), &sa0, &ca0);
    __sincosf(fmaf(xa.y, HPI, h01), &sa1, &ca1);
    __sincosf(fmaf(xa.z, HPI, h02), &sa2, &ca2);
    __sincosf(fmaf(xb.x, HPI, h00), &sb0, &cb0);
    __sincosf(fmaf(xb.y, HPI, h01), &sb1, &cb1);
    __sincosf(fmaf(xb.z, HPI, h02), &sb2, &cb2);

    u64 s0 = pack2(sa0, sb0), c0 = pack2(ca0, cb0);
    u64 s1 = pack2(sa1, sb1), c1 = pack2(ca1, cb1);
    u64 s2 = pack2(sa2, sb2), c2 = pack2(ca2, cb2);

    // Product state amplitudes (both elements in parallel lanes)
    u64 w00 = mul2(c0, c1), w01 = mul2(c0, s1), w10 = mul2(s0, c1), w11 = mul2(s0, s1);
    u64 a000 = mul2(w00, c2), a001 = mul2(w00, s2), a010 = mul2(w01, c2), a011 = mul2(w01, s2);
    u64 a100 = mul2(w10, c2), a101 = mul2(w10, s2), a110 = mul2(w11, c2), a111 = mul2(w11, s2);

    // CNOT(0,1), CNOT(1,2): d[b0][b1][b2] = a[b0][b1^b0][b2^b1]  (renames)
    u64 d000 = a000, d001 = a001, d010 = a011, d011 = a010;
    u64 d100 = a110, d101 = a111, d110 = a101, d111 = a100;

    // Layer-1 RY wire 0
    u64 e000 = fma2(Cx, d000, mul2(NSx, d100));
    u64 e100 = fma2(Sx, d000, mul2(Cx,  d100));
    u64 e001 = fma2(Cx, d001, mul2(NSx, d101));
    u64 e101 = fma2(Sx, d001, mul2(Cx,  d101));
    u64 e010 = fma2(Cx, d010, mul2(NSx, d110));
    u64 e110 = fma2(Sx, d010, mul2(Cx,  d110));
    u64 e011 = fma2(Cx, d011, mul2(NSx, d111));
    u64 e111 = fma2(Sx, d011, mul2(Cx,  d111));

    // wire 1
    u64 f000 = fma2(Cy, e000, mul2(NSy, e010));
    u64 f010 = fma2(Sy, e000, mul2(Cy,  e010));
    u64 f001 = fma2(Cy, e001, mul2(NSy, e011));
    u64 f011 = fma2(Sy, e001, mul2(Cy,  e011));
    u64 f100 = fma2(Cy, e100, mul2(NSy, e110));
    u64 f110 = fma2(Sy, e100, mul2(Cy,  e110));
    u64 f101 = fma2(Cy, e101, mul2(NSy, e111));
    u64 f111 = fma2(Sy, e101, mul2(Cy,  e111));

    // wire 2
    u64 g000 = fma2(Cz, f000, mul2(NSz, f001));
    u64 g001 = fma2(Sz, f000, mul2(Cz,  f001));
    u64 g010 = fma2(Cz, f010, mul2(NSz, f011));
    u64 g011 = fma2(Sz, f010, mul2(Cz,  f011));
    u64 g100 = fma2(Cz, f100, mul2(NSz, f101));
    u64 g101 = fma2(Sz, f100, mul2(Cz,  f101));
    u64 g110 = fma2(Cz, f110, mul2(NSz, f111));
    u64 g111 = fma2(Sz, f110, mul2(Cz,  f111));

    // Probabilities; final CNOT pair folded into sign patterns.
    u64 p000 = mul2(g000, g000), p001 = mul2(g001, g001);
    u64 p010 = mul2(g010, g010), p011 = mul2(g011, g011);
    u64 p100 = mul2(g100, g100), p101 = mul2(g101, g101);
    u64 p110 = mul2(g110, g110), p111 = mul2(g111, g111);

    u64 A = add2(p000, p001), Bp = add2(p010, p011);
    u64 Cp = add2(p100, p101), D = add2(p110, p111);
    u64 z0 = fma2(neg1, add2(Cp, D), add2(A, Bp));
    u64 z1 = fma2(neg1, add2(Bp, Cp), add2(A, D));
    u64 u = fma2(neg1, p001, p000);
    u64 v = fma2(neg1, p011, p010);
    u64 wv = fma2(neg1, p101, p100);
    u64 t = fma2(neg1, p111, p110);
    u64 z2 = add2(fma2(neg1, v, u), fma2(neg1, wv, t));

    float az0, bz0, az1, bz1, az2, bz2;
    unpack2(z0, az0, bz0); unpack2(z1, az1, bz1); unpack2(z2, az2, bz2);

    // 6 contiguous floats -> 3x STG.64 (out + 6*i is 8B-aligned), coalesced.
    float2* o = out + 3 * i;
    o[0] = make_float2(az0, az1);
    o[1] = make_float2(az2, bz0);
    o[2] = make_float2(bz1, bz2);
}

extern "C" void kernel_launch(void* const* d_in, const int* in_sizes, int n_in,
                              void* d_out, int out_size) {
    const float* x = (const float*)d_in[0];   // (B, 4) float32
    const float* w = (const float*)d_in[1];   // (2, 3) float32
    float2* out = (float2*)d_out;             // (B, 3) float32
    int B = in_sizes[0] / 4;
    int T = B / 2;                            // 2 elements per thread

    qfl_kernel<<<(T + 255) / 256, 256>>>((const float4*)x, out, w, T);
}

// round 5
// speedup vs baseline: 1.1601x; 1.0025x over previous
#include <cuda_runtime.h>

// Heisenberg-picture closed form. Pulling Z_i back through the fixed
// CNOT/RY(w1)/CNOT layers gives (Cj=cos θj, Sj=sin θj, θj = x_j*pi + w0_j,
// (A,B,C) = w1, cA=cos A etc.):
//   z0 = cA*C0                         - sA*S0*S1
//   z1 = cA*cB*C1 - cA*sB*C0*S1*S2     + sA*sB*S0*S2
//   z2 = cA*cB*cC*C0*C2 - cA*cB*sC*C1*S2 + cA*sB*sC*C0*S1
//        - sA*cB*cC*S0*S1*C2 - sA*sB*sC*S0
// Y-containing Pauli strings vanish in the real RY product state.
// ~27 FP ops/element -> kernel is HBM-bound (56MB total traffic).

__global__ void __launch_bounds__(256)
qfl_kernel(const float4* __restrict__ x, float2* __restrict__ out,
           const float* __restrict__ w, int T /* = B/2 */) {
    // K[0..2] = w0;  K[3..12] = K1..K10 (weight-only Pauli coefficients)
    __shared__ float K[13];
    if (threadIdx.x == 0) {
        float A = w[3], B = w[4], C = w[5];
        float sA, cA, sB, cB, sC, cC;
        sincosf(A, &sA, &cA);
        sincosf(B, &sB, &cB);
        sincosf(C, &sC, &cC);
        K[0] = w[0]; K[1] = w[1]; K[2] = w[2];
        K[3]  =  cA;                 // z0: C0
        K[4]  = -sA;                 // z0: S0*S1
        K[5]  =  cA * cB;            // z1: C1
        K[6]  = -cA * sB;            // z1: C0*S1*S2
        K[7]  =  sA * sB;            // z1: S0*S2
        K[8]  =  cA * cB * cC;       // z2: C0*C2
        K[9]  = -cA * cB * sC;       // z2: C1*S2
        K[10] =  cA * sB * sC;       // z2: C0*S1
        K[11] = -sA * cB * cC;       // z2: S0*S1*C2
        K[12] = -sA * sB * sC;       // z2: S0
    }
    __syncthreads();

    const float w00 = K[0], w01 = K[1], w02 = K[2];
    const float K1 = K[3], K2 = K[4];
    const float K3 = K[5], K4 = K[6], K5 = K[7];
    const float K6 = K[8], K7 = K[9], K8 = K[10], K9 = K[11], K10 = K[12];

    int i = blockIdx.x * 256 + threadIdx.x;
    if (i >= T) return;

    // Two consecutive elements: 32B contiguous read, front-batched MLP=2.
    const float4 xa = x[2 * i + 0];
    const float4 xb = x[2 * i + 1];

    // Reference uses the literal 3.14159 — match it.
    const float PI_ = 3.14159f;

    float S0a, C0a, S1a, C1a, S2a, C2a;
    float S0b, C0b, S1b, C1b, S2b, C2b;
    __sincosf(fmaf(xa.x, PI_, w00), &S0a, &C0a);
    __sincosf(fmaf(xa.y, PI_, w01), &S1a, &C1a);
    __sincosf(fmaf(xa.z, PI_, w02), &S2a, &C2a);
    __sincosf(fmaf(xb.x, PI_, w00), &S0b, &C0b);
    __sincosf(fmaf(xb.y, PI_, w01), &S1b, &C1b);
    __sincosf(fmaf(xb.z, PI_, w02), &S2b, &C2b);

    // Element a
    float s01a = S0a * S1a;
    float az0 = fmaf(K1, C0a, K2 * s01a);
    float m2a = C0a * (S1a * S2a);
    float az1 = fmaf(K3, C1a, fmaf(K4, m2a, K5 * (S0a * S2a)));
    float az2 = fmaf(K6, C0a * C2a,
                fmaf(K7, C1a * S2a,
                fmaf(K8, C0a * S1a,
                fmaf(K9, s01a * C2a, K10 * S0a))));

    // Element b
    float s01b = S0b * S1b;
    float bz0 = fmaf(K1, C0b, K2 * s01b);
    float m2b = C0b * (S1b * S2b);
    float bz1 = fmaf(K3, C1b, fmaf(K4, m2b, K5 * (S0b * S2b)));
    float bz2 = fmaf(K6, C0b * C2b,
                fmaf(K7, C1b * S2b,
                fmaf(K8, C0b * S1b,
                fmaf(K9, s01b * C2b, K10 * S0b))));

    // 6 contiguous floats -> 3x STG.64, fully coalesced across the warp.
    float2* o = out + 3 * i;
    o[0] = make_float2(az0, az1);
    o[1] = make_float2(az2, bz0);
    o[2] = make_float2(bz1, bz2);
}

extern "C" void kernel_launch(void* const* d_in, const int* in_sizes, int n_in,
                              void* d_out, int out_size) {
    const float* x = (const float*)d_in[0];   // (B, 4) float32
    const float* w = (const float*)d_in[1];   // (2, 3) float32
    float2* out = (float2*)d_out;             // (B, 3) float32
    int B = in_sizes[0] / 4;
    int T = B / 2;                            // 2 elements per thread

    qfl_kernel<<<(T + 255) / 256, 256>>>((const float4*)x, out, w, T);
}